// round 1
// baseline (speedup 1.0000x reference)
#include <cuda_runtime.h>

// Problem constants
#define CIN    256
#define HDIM   256
#define WDIM   256
#define OH     128
#define OW     128
#define HW     (OH*OW)        // 16384
#define YC     1024           // 4 bands * 256 channels
#define COUT   512
#define NGROUP 128
#define GSIZE  8              // channels per group
#define GN_EPS 1e-5f

// ---------------- device scratch (no allocations allowed) ----------------
__device__ float g_y[(size_t)YC * HW];     // 64 MB: raw Haar bands, [c][hw]
__device__ float g_csum[YC];
__device__ float g_csumsq[YC];
__device__ float g_a[YC];                  // per-channel scale  (scale*rstd)
__device__ float g_bsh[YC];                // per-channel shift  (bias - mean*scale*rstd)
__device__ float g_wp[(size_t)COUT * YC];  // folded weights
__device__ float g_biaso[COUT];            // folded per-output bias

// ---------------- packed f32x2 helpers (sm_103a FFMA2 path) ----------------
__device__ __forceinline__ unsigned long long pack2(float lo, float hi) {
    unsigned long long r;
    asm("mov.b64 %0, {%1, %2};" : "=l"(r) : "f"(lo), "f"(hi));
    return r;
}
__device__ __forceinline__ unsigned long long fma2(unsigned long long a,
                                                   unsigned long long b,
                                                   unsigned long long c) {
    unsigned long long d;
    asm("fma.rn.f32x2 %0, %1, %2, %3;" : "=l"(d) : "l"(a), "l"(b), "l"(c));
    return d;
}
__device__ __forceinline__ float2 unpack2(unsigned long long v) {
    float2 r;
    asm("mov.b64 {%0, %1}, %2;" : "=f"(r.x), "=f"(r.y) : "l"(v));
    return r;
}

// ---------------- Kernel A: Haar bands + per-channel sum/sumsq ----------------
// One block per input channel (256 blocks x 256 threads).
__global__ __launch_bounds__(256) void haar_kernel(const float* __restrict__ x) {
    const int cx = blockIdx.x;               // 0..255
    const float* xp = x + (size_t)cx * (HDIM * WDIM);

    float s0 = 0.f, s1 = 0.f, s2 = 0.f, s3 = 0.f;
    float q0 = 0.f, q1 = 0.f, q2 = 0.f, q3 = 0.f;

    for (int i = threadIdx.x; i < HW; i += 256) {
        const int h = i >> 7;        // 0..127
        const int w = i & 127;       // 0..127
        const float2 r0 = *((const float2*)(xp + (size_t)(2 * h) * WDIM) + w);
        const float2 r1 = *((const float2*)(xp + (size_t)(2 * h + 1) * WDIM) + w);
        const float x00 = r0.x, x01 = r0.y, x10 = r1.x, x11 = r1.y;
        const float ll = 0.5f * ( x00 + x01 + x10 + x11);
        const float hl = 0.5f * (-x00 - x01 + x10 + x11);
        const float lh = 0.5f * (-x00 + x01 - x10 + x11);
        const float hh = 0.5f * ( x00 - x01 - x10 + x11);

        const size_t base = (size_t)cx * HW + i;
        g_y[base]                      = ll;
        g_y[(size_t)256 * HW + base]   = hl;
        g_y[(size_t)512 * HW + base]   = lh;
        g_y[(size_t)768 * HW + base]   = hh;

        s0 += ll; q0 += ll * ll;
        s1 += hl; q1 += hl * hl;
        s2 += lh; q2 += lh * lh;
        s3 += hh; q3 += hh * hh;
    }

    __shared__ float red[256];
    float vals[8] = {s0, s1, s2, s3, q0, q1, q2, q3};
    for (int q = 0; q < 8; q++) {
        red[threadIdx.x] = vals[q];
        __syncthreads();
        for (int off = 128; off > 0; off >>= 1) {
            if (threadIdx.x < off) red[threadIdx.x] += red[threadIdx.x + off];
            __syncthreads();
        }
        if (threadIdx.x == 0) {
            const int band = q & 3;
            if (q < 4) g_csum[band * 256 + cx]   = red[0];
            else       g_csumsq[band * 256 + cx] = red[0];
        }
        __syncthreads();
    }
}

// ---------------- Kernel B: group stats -> per-channel affine ----------------
__global__ void stats_kernel(const float* __restrict__ scale,
                             const float* __restrict__ bias) {
    const int g = threadIdx.x;               // 0..127
    float s = 0.f, q = 0.f;
    #pragma unroll
    for (int j = 0; j < GSIZE; j++) {
        const int c = g * GSIZE + j;
        s += g_csum[c];
        q += g_csumsq[c];
    }
    const float inv  = 1.0f / (float)(GSIZE * HW);   // 1/131072
    const float mean = s * inv;
    const float var  = q * inv - mean * mean;
    const float rstd = rsqrtf(var + GN_EPS);
    #pragma unroll
    for (int j = 0; j < GSIZE; j++) {
        const int c = g * GSIZE + j;
        const float a = scale[c] * rstd;
        g_a[c]   = a;
        g_bsh[c] = bias[c] - mean * a;
    }
}

// ---------------- Kernel C: fold affine into weights + output bias ----------------
__global__ __launch_bounds__(256) void foldw_kernel(const float* __restrict__ w) {
    const int o = blockIdx.x;                // 0..511
    float part = 0.f;
    for (int c = threadIdx.x; c < YC; c += 256) {
        const float wv = w[(size_t)o * YC + c];
        g_wp[(size_t)o * YC + c] = wv * g_a[c];
        part += wv * g_bsh[c];
    }
    __shared__ float red[256];
    red[threadIdx.x] = part;
    __syncthreads();
    for (int off = 128; off > 0; off >>= 1) {
        if (threadIdx.x < off) red[threadIdx.x] += red[threadIdx.x + off];
        __syncthreads();
    }
    if (threadIdx.x == 0) g_biaso[o] = red[0];
}

// ---------------- Kernel D: SGEMM (f32x2 packed FMA) + bias + ReLU ----------------
// C[512,16384] = g_wp[512,1024] @ g_y[1024,16384]
#define BM 128
#define BN 128
#define BK 16
#define APAD 4

__global__ __launch_bounds__(256) void gemm_relu_kernel(float* __restrict__ out) {
    const int K = YC;       // 1024
    const int N = HW;       // 16384

    __shared__ float As[BK][BM + APAD];   // transposed A tile (padded vs conflicts)
    __shared__ float Bs[BK][BN];

    const int tid = threadIdx.x;
    const int tx = tid & 15;       // 0..15 -> 8 cols each
    const int ty = tid >> 4;       // 0..15 -> 8 rows each
    const int bx = blockIdx.x;     // 0..127 (N tiles)
    const int by = blockIdx.y;     // 0..3   (M tiles)

    // global load mapping
    const int a_r = tid >> 2;            // 0..63  (+64 for 2nd half)
    const int a_c = (tid & 3) * 4;       // 0,4,8,12
    const float* Ap = g_wp + (size_t)(by * BM + a_r) * K + a_c;
    const int b_r = tid >> 5;            // 0..7   (+8 for 2nd half)
    const int b_c = (tid & 31) * 4;      // 0..124
    const float* Bp = g_y + (size_t)b_r * N + (size_t)bx * BN + b_c;

    unsigned long long acc[8][4];
    #pragma unroll
    for (int i = 0; i < 8; i++)
        #pragma unroll
        for (int j = 0; j < 4; j++) acc[i][j] = pack2(0.f, 0.f);

    // preload tile 0
    float4 ar0 = *(const float4*)(Ap);
    float4 ar1 = *(const float4*)(Ap + (size_t)64 * K);
    float4 br0 = *(const float4*)(Bp);
    float4 br1 = *(const float4*)(Bp + (size_t)8 * N);

    for (int kt = 0; kt < K; kt += BK) {
        // stage regs -> smem
        As[a_c + 0][a_r] = ar0.x;
        As[a_c + 1][a_r] = ar0.y;
        As[a_c + 2][a_r] = ar0.z;
        As[a_c + 3][a_r] = ar0.w;
        As[a_c + 0][a_r + 64] = ar1.x;
        As[a_c + 1][a_r + 64] = ar1.y;
        As[a_c + 2][a_r + 64] = ar1.z;
        As[a_c + 3][a_r + 64] = ar1.w;
        *(float4*)&Bs[b_r][b_c]     = br0;
        *(float4*)&Bs[b_r + 8][b_c] = br1;
        __syncthreads();

        // prefetch next tile (hidden under the compute below)
        if (kt + BK < K) {
            ar0 = *(const float4*)(Ap + kt + BK);
            ar1 = *(const float4*)(Ap + (size_t)64 * K + kt + BK);
            br0 = *(const float4*)(Bp + (size_t)(kt + BK) * N);
            br1 = *(const float4*)(Bp + (size_t)(kt + BK + 8) * N);
        }

        #pragma unroll
        for (int k = 0; k < BK; k++) {
            const float4 a0 = *(const float4*)&As[k][ty * 8];
            const float4 a1 = *(const float4*)&As[k][ty * 8 + 4];
            const float4 b0 = *(const float4*)&Bs[k][tx * 8];
            const float4 b1 = *(const float4*)&Bs[k][tx * 8 + 4];

            const unsigned long long bb0 = pack2(b0.x, b0.y);
            const unsigned long long bb1 = pack2(b0.z, b0.w);
            const unsigned long long bb2 = pack2(b1.x, b1.y);
            const unsigned long long bb3 = pack2(b1.z, b1.w);
            const float av[8] = {a0.x, a0.y, a0.z, a0.w, a1.x, a1.y, a1.z, a1.w};

            #pragma unroll
            for (int i = 0; i < 8; i++) {
                const unsigned long long ai = pack2(av[i], av[i]);
                acc[i][0] = fma2(ai, bb0, acc[i][0]);
                acc[i][1] = fma2(ai, bb1, acc[i][1]);
                acc[i][2] = fma2(ai, bb2, acc[i][2]);
                acc[i][3] = fma2(ai, bb3, acc[i][3]);
            }
        }
        __syncthreads();
    }

    // epilogue: +bias, ReLU, vectorized store
    const int row0 = by * BM + ty * 8;
    const int col0 = bx * BN + tx * 8;
    #pragma unroll
    for (int i = 0; i < 8; i++) {
        const float bi = g_biaso[row0 + i];
        const float2 v0 = unpack2(acc[i][0]);
        const float2 v1 = unpack2(acc[i][1]);
        const float2 v2 = unpack2(acc[i][2]);
        const float2 v3 = unpack2(acc[i][3]);
        float4 o0, o1;
        o0.x = fmaxf(v0.x + bi, 0.f); o0.y = fmaxf(v0.y + bi, 0.f);
        o0.z = fmaxf(v1.x + bi, 0.f); o0.w = fmaxf(v1.y + bi, 0.f);
        o1.x = fmaxf(v2.x + bi, 0.f); o1.y = fmaxf(v2.y + bi, 0.f);
        o1.z = fmaxf(v3.x + bi, 0.f); o1.w = fmaxf(v3.y + bi, 0.f);
        float* cp = out + (size_t)(row0 + i) * N + col0;
        *(float4*)cp       = o0;
        *(float4*)(cp + 4) = o1;
    }
}

// ---------------- launch ----------------
extern "C" void kernel_launch(void* const* d_in, const int* in_sizes, int n_in,
                              void* d_out, int out_size) {
    const float* x        = (const float*)d_in[0];
    const float* gn_scale = (const float*)d_in[1];
    const float* gn_bias  = (const float*)d_in[2];
    const float* w_proj   = (const float*)d_in[3];
    float* out = (float*)d_out;

    haar_kernel<<<CIN, 256>>>(x);
    stats_kernel<<<1, NGROUP>>>(gn_scale, gn_bias);
    foldw_kernel<<<COUT, 256>>>(w_proj);
    dim3 grid(HW / BN, COUT / BM);
    gemm_relu_kernel<<<grid, 256>>>(out);
}

// round 3
// speedup vs baseline: 2.2451x; 2.2451x over previous
#include <cuda_runtime.h>
#include <cuda_bf16.h>
#include <cstdint>

// ---------------- problem constants ----------------
#define HDIM   256
#define WDIM   256
#define HW     16384          // 128*128 output pixels
#define KPHYS  2048           // [W1|W2] cols / [Y1;Y2] rows
#define COUT   512
#define NGROUP 128
#define GSIZE  8
#define GN_EPS 1e-5f
#define TITER  96             // 3072 logical K / 32

// ---------------- device scratch ----------------
__device__ __nv_bfloat16 g_B[(size_t)KPHYS * HW];   // 64 MB: rows 0-1023 Y1(hi), 1024-2047 Y2(lo), [k][n]
__device__ __nv_bfloat16 g_A[(size_t)COUT * KPHYS]; // 2 MB: cols 0-1023 W1(hi), 1024-2047 W2(lo), [o][k]
__device__ float g_csum[1024];
__device__ float g_csumsq[1024];
__device__ float g_a[1024];
__device__ float g_bsh[1024];
__device__ float g_biaso[COUT];

// ---------------- PTX helpers (all target-generic, no sm_103a-only ops) -------
__device__ __forceinline__ uint32_t s2u(const void* p) {
    uint32_t a;
    asm("{ .reg .u64 t; cvta.to.shared.u64 t, %1; cvt.u32.u64 %0, t; }" : "=r"(a) : "l"(p));
    return a;
}
__device__ __forceinline__ void cp16(uint32_t dst, const void* src) {
    asm volatile("cp.async.cg.shared.global [%0], [%1], 16;" :: "r"(dst), "l"(src));
}
__device__ __forceinline__ void cp_commit() {
    asm volatile("cp.async.commit_group;" ::: "memory");
}
__device__ __forceinline__ void cp_wait2() {
    asm volatile("cp.async.wait_group 2;" ::: "memory");
}
__device__ __forceinline__ void ldsm4(uint32_t* r, uint32_t a) {
    asm volatile("ldmatrix.sync.aligned.m8n8.x4.shared.b16 {%0,%1,%2,%3}, [%4];"
                 : "=r"(r[0]), "=r"(r[1]), "=r"(r[2]), "=r"(r[3]) : "r"(a));
}
__device__ __forceinline__ void ldsm4t(uint32_t* r, uint32_t a) {
    asm volatile("ldmatrix.sync.aligned.m8n8.x4.trans.shared.b16 {%0,%1,%2,%3}, [%4];"
                 : "=r"(r[0]), "=r"(r[1]), "=r"(r[2]), "=r"(r[3]) : "r"(a));
}
__device__ __forceinline__ void mma16816(float* d, const uint32_t* a, uint32_t b0, uint32_t b1) {
    asm volatile(
        "mma.sync.aligned.m16n8k16.row.col.f32.bf16.bf16.f32 "
        "{%0,%1,%2,%3}, {%4,%5,%6,%7}, {%8,%9}, {%0,%1,%2,%3};"
        : "+f"(d[0]), "+f"(d[1]), "+f"(d[2]), "+f"(d[3])
        : "r"(a[0]), "r"(a[1]), "r"(a[2]), "r"(a[3]), "r"(b0), "r"(b1));
}

// ---------------- Kernel A: Haar bands -> bf16 hi/lo split + stats ----------------
__global__ __launch_bounds__(256) void haar_kernel(const float* __restrict__ x) {
    const int cx = blockIdx.x;               // input channel 0..255
    const float* xp = x + (size_t)cx * (HDIM * WDIM);

    float s0=0.f,s1=0.f,s2=0.f,s3=0.f,q0=0.f,q1=0.f,q2=0.f,q3=0.f;

    for (int i2 = threadIdx.x * 2; i2 < HW; i2 += 512) {
        const int h = i2 >> 7;
        const int w = i2 & 127;               // even
        const float4 r0 = *(const float4*)(xp + (size_t)(2*h)   * WDIM + 2*w);
        const float4 r1 = *(const float4*)(xp + (size_t)(2*h+1) * WDIM + 2*w);
        float v0[4], v1[4];
        v0[0] = 0.5f*( r0.x + r0.y + r1.x + r1.y);
        v0[1] = 0.5f*(-r0.x - r0.y + r1.x + r1.y);
        v0[2] = 0.5f*(-r0.x + r0.y - r1.x + r1.y);
        v0[3] = 0.5f*( r0.x - r0.y - r1.x + r1.y);
        v1[0] = 0.5f*( r0.z + r0.w + r1.z + r1.w);
        v1[1] = 0.5f*(-r0.z - r0.w + r1.z + r1.w);
        v1[2] = 0.5f*(-r0.z + r0.w - r1.z + r1.w);
        v1[3] = 0.5f*( r0.z - r0.w - r1.z + r1.w);
        s0 += v0[0]+v1[0]; q0 += v0[0]*v0[0] + v1[0]*v1[0];
        s1 += v0[1]+v1[1]; q1 += v0[1]*v0[1] + v1[1]*v1[1];
        s2 += v0[2]+v1[2]; q2 += v0[2]*v0[2] + v1[2]*v1[2];
        s3 += v0[3]+v1[3]; q3 += v0[3]*v0[3] + v1[3]*v1[3];
        #pragma unroll
        for (int b = 0; b < 4; b++) {
            const size_t c = (size_t)b * 256 + cx;
            const __nv_bfloat16 h0 = __float2bfloat16_rn(v0[b]);
            const __nv_bfloat16 h1 = __float2bfloat16_rn(v1[b]);
            const __nv_bfloat16 l0 = __float2bfloat16_rn(v0[b] - __bfloat162float(h0));
            const __nv_bfloat16 l1 = __float2bfloat16_rn(v1[b] - __bfloat162float(h1));
            *(__nv_bfloat162*)&g_B[c * HW + i2]          = __nv_bfloat162(h0, h1);
            *(__nv_bfloat162*)&g_B[(c + 1024) * HW + i2] = __nv_bfloat162(l0, l1);
        }
    }

    __shared__ float red[256];
    float vals[8] = {s0,s1,s2,s3,q0,q1,q2,q3};
    for (int q = 0; q < 8; q++) {
        red[threadIdx.x] = vals[q];
        __syncthreads();
        for (int off = 128; off > 0; off >>= 1) {
            if (threadIdx.x < off) red[threadIdx.x] += red[threadIdx.x + off];
            __syncthreads();
        }
        if (threadIdx.x == 0) {
            const int band = q & 3;
            if (q < 4) g_csum[band*256 + cx]   = red[0];
            else       g_csumsq[band*256 + cx] = red[0];
        }
        __syncthreads();
    }
}

// ---------------- Kernel B: group stats -> per-channel affine ----------------
__global__ void stats_kernel(const float* __restrict__ scale,
                             const float* __restrict__ bias) {
    const int g = threadIdx.x;               // 0..127
    float s = 0.f, q = 0.f;
    #pragma unroll
    for (int j = 0; j < GSIZE; j++) { s += g_csum[g*GSIZE+j]; q += g_csumsq[g*GSIZE+j]; }
    const float inv  = 1.0f / (float)(GSIZE * HW);
    const float mean = s * inv;
    const float var  = q * inv - mean * mean;
    const float rstd = rsqrtf(var + GN_EPS);
    #pragma unroll
    for (int j = 0; j < GSIZE; j++) {
        const int c = g*GSIZE + j;
        const float a = scale[c] * rstd;
        g_a[c]   = a;
        g_bsh[c] = bias[c] - mean * a;
    }
}

// ---------------- Kernel C: fold affine into weights, split to bf16 ----------------
__global__ __launch_bounds__(256) void foldw_kernel(const float* __restrict__ w) {
    const int o = blockIdx.x;                // 0..511
    float part = 0.f;
    for (int c = threadIdx.x; c < 1024; c += 256) {
        const float wv = w[(size_t)o * 1024 + c];
        const float v  = wv * g_a[c];
        const __nv_bfloat16 hi = __float2bfloat16_rn(v);
        g_A[(size_t)o * KPHYS + c]        = hi;
        g_A[(size_t)o * KPHYS + 1024 + c] = __float2bfloat16_rn(v - __bfloat162float(hi));
        part += wv * g_bsh[c];
    }
    __shared__ float red[256];
    red[threadIdx.x] = part;
    __syncthreads();
    for (int off = 128; off > 0; off >>= 1) {
        if (threadIdx.x < off) red[threadIdx.x] += red[threadIdx.x + off];
        __syncthreads();
    }
    if (threadIdx.x == 0) g_biaso[o] = red[0];
}

// ---------------- Kernel D: mma.sync bf16 GEMM + bias + ReLU ----------------
// C[512,16384] = A[512,3072] @ B[3072,16384]; BM=128 BN=128 BK=32, 8 warps 64x32.
// SMEM per stage: A 8KB + B 8KB = 16KB; 4 stages = 64KB dynamic.
#define STAGE_BYTES 16384
#define GEMM_SMEM   (4 * STAGE_BYTES)

__device__ __forceinline__ void load_stage(int tid, int j, uint32_t sbase, int m0, int n0) {
    const uint32_t st = sbase + (uint32_t)(j & 3) * STAGE_BYTES;
    const int seg  = j >> 5;                 // 0,1,2
    const int koff = (j & 31) << 5;          // 0..992
    const int a_col = ((seg == 2) ? 1024 : 0) + koff;
    const int b_row = ((seg == 1) ? 1024 : 0) + koff;
    const __nv_bfloat16* Ab = g_A + (size_t)m0 * KPHYS + a_col;
    const __nv_bfloat16* Bb = g_B + (size_t)b_row * HW + n0;
    // A: 128 rows(m) x 4 chunks(kc of 8 bf16). swizzled unit = m*4 + (kc ^ ((m>>1)&3))
    #pragma unroll
    for (int t = 0; t < 2; t++) {
        const int u = tid + t * 256;
        const int m = u >> 2, kc = u & 3;
        const uint32_t du = (uint32_t)(m * 4 + (kc ^ ((m >> 1) & 3)));
        cp16(st + du * 16, Ab + (size_t)m * KPHYS + kc * 8);
    }
    // B: 32 rows(k) x 16 chunks(nc of 8 bf16). swizzled unit = k*16 + (nc ^ (k&7))
    #pragma unroll
    for (int t = 0; t < 2; t++) {
        const int u = tid + t * 256;
        const int k = u >> 4, nc = u & 15;
        const uint32_t du = (uint32_t)(k * 16 + (nc ^ (k & 7)));
        cp16(st + 8192 + du * 16, Bb + (size_t)k * HW + nc * 8);
    }
}

__global__ __launch_bounds__(256, 2) void gemm_mma_kernel(float* __restrict__ out) {
    extern __shared__ char smem[];
    const uint32_t sbase = s2u(smem);
    const int tid  = threadIdx.x;
    const int wid  = tid >> 5;
    const int lane = tid & 31;
    const int n0 = blockIdx.x * 128;
    const int m0 = blockIdx.y * 128;
    const int wm = wid >> 2;                 // 0..1
    const int wn = wid & 3;                  // 0..3
    const int mbase = wm * 64;
    const int nbase = wn * 32;

    float acc[4][4][4];
    #pragma unroll
    for (int i = 0; i < 4; i++)
        #pragma unroll
        for (int j = 0; j < 4; j++)
            #pragma unroll
            for (int q = 0; q < 4; q++) acc[i][j][q] = 0.f;

    load_stage(tid, 0, sbase, m0, n0); cp_commit();
    load_stage(tid, 1, sbase, m0, n0); cp_commit();
    load_stage(tid, 2, sbase, m0, n0); cp_commit();

    const int r15 = lane & 15;
    const int hi  = lane >> 4;
    const int sA  = (r15 >> 1) & 3;          // A swizzle term

    for (int j = 0; j < TITER; j++) {
        cp_wait2();
        __syncthreads();
        if (j + 3 < TITER) load_stage(tid, j + 3, sbase, m0, n0);
        cp_commit();

        const uint32_t st = sbase + (uint32_t)(j & 3) * STAGE_BYTES;
        #pragma unroll
        for (int kk = 0; kk < 2; kk++) {
            uint32_t a[4][4];
            #pragma unroll
            for (int mf = 0; mf < 4; mf++) {
                const int row = mbase + mf * 16 + r15;
                const uint32_t addr = st +
                    (uint32_t)((row * 4 + ((kk * 2 + hi) ^ sA)) * 16);
                ldsm4(a[mf], addr);
            }
            uint32_t b[2][4];
            #pragma unroll
            for (int p = 0; p < 2; p++) {
                const int k   = kk * 16 + r15;
                const int ncg = wn * 4 + p * 2 + hi;
                const uint32_t addr = st + 8192 +
                    (uint32_t)((k * 16 + (ncg ^ (lane & 7))) * 16);
                ldsm4t(b[p], addr);
            }
            #pragma unroll
            for (int mf = 0; mf < 4; mf++)
                #pragma unroll
                for (int nf = 0; nf < 4; nf++)
                    mma16816(acc[mf][nf], a[mf], b[nf >> 1][(nf & 1) * 2],
                             b[nf >> 1][(nf & 1) * 2 + 1]);
        }
    }

    // epilogue: bias + ReLU + float2 stores
    const int qrow = lane >> 2;
    const int qcol = (lane & 3) * 2;
    #pragma unroll
    for (int mf = 0; mf < 4; mf++) {
        const int row0 = m0 + mbase + mf * 16 + qrow;
        const float bi0 = g_biaso[row0];
        const float bi1 = g_biaso[row0 + 8];
        float* o0 = out + (size_t)row0 * HW + n0 + nbase + qcol;
        float* o1 = out + (size_t)(row0 + 8) * HW + n0 + nbase + qcol;
        #pragma unroll
        for (int nf = 0; nf < 4; nf++) {
            float2 v0, v1;
            v0.x = fmaxf(acc[mf][nf][0] + bi0, 0.f);
            v0.y = fmaxf(acc[mf][nf][1] + bi0, 0.f);
            v1.x = fmaxf(acc[mf][nf][2] + bi1, 0.f);
            v1.y = fmaxf(acc[mf][nf][3] + bi1, 0.f);
            *(float2*)(o0 + nf * 8) = v0;
            *(float2*)(o1 + nf * 8) = v1;
        }
    }
}

// ---------------- launch ----------------
extern "C" void kernel_launch(void* const* d_in, const int* in_sizes, int n_in,
                              void* d_out, int out_size) {
    const float* x        = (const float*)d_in[0];
    const float* gn_scale = (const float*)d_in[1];
    const float* gn_bias  = (const float*)d_in[2];
    const float* w_proj   = (const float*)d_in[3];
    float* out = (float*)d_out;

    static bool attr_set = false;
    if (!attr_set) {
        cudaFuncSetAttribute(gemm_mma_kernel,
                             cudaFuncAttributeMaxDynamicSharedMemorySize, GEMM_SMEM);
        attr_set = true;
    }

    haar_kernel<<<256, 256>>>(x);
    stats_kernel<<<1, NGROUP>>>(gn_scale, gn_bias);
    foldw_kernel<<<COUT, 256>>>(w_proj);
    dim3 grid(HW / 128, COUT / 128);
    gemm_mma_kernel<<<grid, 256, GEMM_SMEM>>>(out);
}

// round 4
// speedup vs baseline: 3.1950x; 1.4231x over previous
#include <cuda_runtime.h>
#include <cuda_fp16.h>
#include <cstdint>

// ---------------- problem constants ----------------
#define HDIM   256
#define WDIM   256
#define HW     16384          // 128*128 output pixels
#define KB     1024           // physical K (channels)
#define COUT   512
#define NGROUP 128
#define GSIZE  8
#define GN_EPS 1e-5f
#define TITER  32             // 1024 physical K / 32 (each tile does W1+W2 MMAs)

// ---------------- device scratch ----------------
__device__ __half g_B[(size_t)KB * HW];        // 32 MB: Y fp16, [k][n]
__device__ __half g_A[(size_t)COUT * 2 * KB];  // 2 MB: [o][0..1023]=W1(hi), [o][1024..2047]=W2(lo)
__device__ float g_csum[KB];
__device__ float g_csumsq[KB];
__device__ float g_biaso[COUT];

// ---------------- PTX helpers (target-generic only) ----------------
__device__ __forceinline__ uint32_t s2u(const void* p) {
    uint32_t a;
    asm("{ .reg .u64 t; cvta.to.shared.u64 t, %1; cvt.u32.u64 %0, t; }" : "=r"(a) : "l"(p));
    return a;
}
__device__ __forceinline__ void cp16(uint32_t dst, const void* src) {
    asm volatile("cp.async.cg.shared.global [%0], [%1], 16;" :: "r"(dst), "l"(src));
}
__device__ __forceinline__ void cp_commit() {
    asm volatile("cp.async.commit_group;" ::: "memory");
}
__device__ __forceinline__ void cp_wait2() {
    asm volatile("cp.async.wait_group 2;" ::: "memory");
}
__device__ __forceinline__ void ldsm4(uint32_t* r, uint32_t a) {
    asm volatile("ldmatrix.sync.aligned.m8n8.x4.shared.b16 {%0,%1,%2,%3}, [%4];"
                 : "=r"(r[0]), "=r"(r[1]), "=r"(r[2]), "=r"(r[3]) : "r"(a));
}
__device__ __forceinline__ void ldsm4t(uint32_t* r, uint32_t a) {
    asm volatile("ldmatrix.sync.aligned.m8n8.x4.trans.shared.b16 {%0,%1,%2,%3}, [%4];"
                 : "=r"(r[0]), "=r"(r[1]), "=r"(r[2]), "=r"(r[3]) : "r"(a));
}
__device__ __forceinline__ void mma16816(float* d, const uint32_t* a, uint32_t b0, uint32_t b1) {
    asm volatile(
        "mma.sync.aligned.m16n8k16.row.col.f32.f16.f16.f32 "
        "{%0,%1,%2,%3}, {%4,%5,%6,%7}, {%8,%9}, {%0,%1,%2,%3};"
        : "+f"(d[0]), "+f"(d[1]), "+f"(d[2]), "+f"(d[3])
        : "r"(a[0]), "r"(a[1]), "r"(a[2]), "r"(a[3]), "r"(b0), "r"(b1));
}

// ---------------- Kernel A: Haar bands -> fp16 + stats ----------------
__global__ __launch_bounds__(256) void haar_kernel(const float* __restrict__ x) {
    const int cx = blockIdx.x;               // input channel 0..255
    const float* xp = x + (size_t)cx * (HDIM * WDIM);

    float s0=0.f,s1=0.f,s2=0.f,s3=0.f,q0=0.f,q1=0.f,q2=0.f,q3=0.f;

    for (int i2 = threadIdx.x * 2; i2 < HW; i2 += 512) {
        const int h = i2 >> 7;
        const int w = i2 & 127;               // even
        const float4 r0 = *(const float4*)(xp + (size_t)(2*h)   * WDIM + 2*w);
        const float4 r1 = *(const float4*)(xp + (size_t)(2*h+1) * WDIM + 2*w);
        float v0[4], v1[4];
        v0[0] = 0.5f*( r0.x + r0.y + r1.x + r1.y);
        v0[1] = 0.5f*(-r0.x - r0.y + r1.x + r1.y);
        v0[2] = 0.5f*(-r0.x + r0.y - r1.x + r1.y);
        v0[3] = 0.5f*( r0.x - r0.y - r1.x + r1.y);
        v1[0] = 0.5f*( r0.z + r0.w + r1.z + r1.w);
        v1[1] = 0.5f*(-r0.z - r0.w + r1.z + r1.w);
        v1[2] = 0.5f*(-r0.z + r0.w - r1.z + r1.w);
        v1[3] = 0.5f*( r0.z - r0.w - r1.z + r1.w);
        s0 += v0[0]+v1[0]; q0 += v0[0]*v0[0] + v1[0]*v1[0];
        s1 += v0[1]+v1[1]; q1 += v0[1]*v0[1] + v1[1]*v1[1];
        s2 += v0[2]+v1[2]; q2 += v0[2]*v0[2] + v1[2]*v1[2];
        s3 += v0[3]+v1[3]; q3 += v0[3]*v0[3] + v1[3]*v1[3];
        #pragma unroll
        for (int b = 0; b < 4; b++) {
            const size_t c = (size_t)b * 256 + cx;
            *(__half2*)&g_B[c * HW + i2] =
                __halves2half2(__float2half_rn(v0[b]), __float2half_rn(v1[b]));
        }
    }

    __shared__ float red[256];
    float vals[8] = {s0,s1,s2,s3,q0,q1,q2,q3};
    for (int q = 0; q < 8; q++) {
        red[threadIdx.x] = vals[q];
        __syncthreads();
        for (int off = 128; off > 0; off >>= 1) {
            if (threadIdx.x < off) red[threadIdx.x] += red[threadIdx.x + off];
            __syncthreads();
        }
        if (threadIdx.x == 0) {
            const int band = q & 3;
            if (q < 4) g_csum[band*256 + cx]   = red[0];
            else       g_csumsq[band*256 + cx] = red[0];
        }
        __syncthreads();
    }
}

// ---------------- Kernel B: stats + fold affine into weights (fp16 split) ------
__global__ __launch_bounds__(256) void foldw_kernel(const float* __restrict__ w,
                                                    const float* __restrict__ scale,
                                                    const float* __restrict__ bias) {
    __shared__ float sa[KB], sb[KB];
    const int tid = threadIdx.x;
    if (tid < NGROUP) {
        const int g = tid;
        float s = 0.f, q = 0.f;
        #pragma unroll
        for (int j = 0; j < GSIZE; j++) { s += g_csum[g*GSIZE+j]; q += g_csumsq[g*GSIZE+j]; }
        const float inv  = 1.0f / (float)(GSIZE * HW);
        const float mean = s * inv;
        const float var  = q * inv - mean * mean;
        const float rstd = rsqrtf(var + GN_EPS);
        #pragma unroll
        for (int j = 0; j < GSIZE; j++) {
            const int c = g*GSIZE + j;
            const float a = scale[c] * rstd;
            sa[c] = a;
            sb[c] = bias[c] - mean * a;
        }
    }
    __syncthreads();

    const int o = blockIdx.x;                // 0..511
    float part = 0.f;
    for (int c = tid; c < KB; c += 256) {
        const float wv = w[(size_t)o * KB + c];
        const float v  = wv * sa[c];
        const __half hi = __float2half_rn(v);
        g_A[(size_t)o * (2*KB) + c]      = hi;
        g_A[(size_t)o * (2*KB) + KB + c] = __float2half_rn(v - __half2float(hi));
        part += wv * sb[c];
    }
    __shared__ float red[256];
    red[tid] = part;
    __syncthreads();
    for (int off = 128; off > 0; off >>= 1) {
        if (tid < off) red[tid] += red[tid + off];
        __syncthreads();
    }
    if (tid == 0) g_biaso[o] = red[0];
}

// ---------------- Kernel C: mma.sync fp16 GEMM (W split fused) + bias + ReLU ----
// C[512,16384] = (W1+W2)[512,1024] @ Y[1024,16384]; BM=128 BN=128 BK=32.
// Stage: A1 8KB + A2 8KB + B 8KB = 24KB; 4 stages = 96KB.
#define STAGE_BYTES 24576
#define GEMM_SMEM   (4 * STAGE_BYTES)

__device__ __forceinline__ void load_stage(int tid, int j, uint32_t sbase, int m0, int n0) {
    const uint32_t st = sbase + (uint32_t)(j & 3) * STAGE_BYTES;
    const int koff = j << 5;                 // 0..992
    const __half* A1 = g_A + (size_t)m0 * (2*KB) + koff;
    const __half* Bb = g_B + (size_t)koff * HW + n0;
    // A halves: 128 rows(m) x 4 chunks(kc of 8 halves); swizzle unit = m*4 + (kc ^ ((m>>1)&3))
    #pragma unroll
    for (int t = 0; t < 2; t++) {
        const int u = tid + t * 256;
        const int m = u >> 2, kc = u & 3;
        const uint32_t du = (uint32_t)(m * 4 + (kc ^ ((m >> 1) & 3))) * 16;
        const size_t go = (size_t)m * (2*KB) + kc * 8;
        cp16(st + du,        A1 + go);        // W1
        cp16(st + 8192 + du, A1 + KB + go);   // W2
    }
    // B: 32 rows(k) x 16 chunks(nc of 8 halves); swizzle unit = k*16 + (nc ^ (k&7))
    #pragma unroll
    for (int t = 0; t < 2; t++) {
        const int u = tid + t * 256;
        const int k = u >> 4, nc = u & 15;
        const uint32_t du = (uint32_t)(k * 16 + (nc ^ (k & 7)));
        cp16(st + 16384 + du * 16, Bb + (size_t)k * HW + nc * 8);
    }
}

__global__ __launch_bounds__(256, 2) void gemm_mma_kernel(float* __restrict__ out) {
    extern __shared__ char smem[];
    const uint32_t sbase = s2u(smem);
    const int tid  = threadIdx.x;
    const int wid  = tid >> 5;
    const int lane = tid & 31;
    const int n0 = blockIdx.x * 128;
    const int m0 = blockIdx.y * 128;
    const int wm = wid >> 2;                 // 0..1
    const int wn = wid & 3;                  // 0..3
    const int mbase = wm * 64;
    const int nbase = wn * 32;

    float acc[4][4][4];
    #pragma unroll
    for (int i = 0; i < 4; i++)
        #pragma unroll
        for (int j = 0; j < 4; j++)
            #pragma unroll
            for (int q = 0; q < 4; q++) acc[i][j][q] = 0.f;

    load_stage(tid, 0, sbase, m0, n0); cp_commit();
    load_stage(tid, 1, sbase, m0, n0); cp_commit();
    load_stage(tid, 2, sbase, m0, n0); cp_commit();

    const int r15 = lane & 15;
    const int hi  = lane >> 4;
    const int sA  = (r15 >> 1) & 3;          // A swizzle term

    for (int j = 0; j < TITER; j++) {
        cp_wait2();
        __syncthreads();
        if (j + 3 < TITER) load_stage(tid, j + 3, sbase, m0, n0);
        cp_commit();

        const uint32_t st = sbase + (uint32_t)(j & 3) * STAGE_BYTES;
        #pragma unroll
        for (int kk = 0; kk < 2; kk++) {
            const uint32_t aoff = (uint32_t)(((mbase + r15) * 4 + ((kk * 2 + hi) ^ sA)) * 16);
            uint32_t b[2][4];
            #pragma unroll
            for (int p = 0; p < 2; p++) {
                const int k   = kk * 16 + r15;
                const int ncg = wn * 4 + p * 2 + hi;
                ldsm4t(b[p], st + 16384 + (uint32_t)((k * 16 + (ncg ^ (lane & 7))) * 16));
            }
            uint32_t a1[4][4];
            #pragma unroll
            for (int mf = 0; mf < 4; mf++) ldsm4(a1[mf], st + aoff + (uint32_t)(mf * 1024));
            #pragma unroll
            for (int mf = 0; mf < 4; mf++)
                #pragma unroll
                for (int nf = 0; nf < 4; nf++)
                    mma16816(acc[mf][nf], a1[mf], b[nf >> 1][(nf & 1) * 2],
                             b[nf >> 1][(nf & 1) * 2 + 1]);
            uint32_t a2[4][4];
            #pragma unroll
            for (int mf = 0; mf < 4; mf++) ldsm4(a2[mf], st + 8192 + aoff + (uint32_t)(mf * 1024));
            #pragma unroll
            for (int mf = 0; mf < 4; mf++)
                #pragma unroll
                for (int nf = 0; nf < 4; nf++)
                    mma16816(acc[mf][nf], a2[mf], b[nf >> 1][(nf & 1) * 2],
                             b[nf >> 1][(nf & 1) * 2 + 1]);
        }
    }

    // epilogue: bias + ReLU + float2 stores
    const int qrow = lane >> 2;
    const int qcol = (lane & 3) * 2;
    #pragma unroll
    for (int mf = 0; mf < 4; mf++) {
        const int row0 = m0 + mbase + mf * 16 + qrow;
        const float bi0 = g_biaso[row0];
        const float bi1 = g_biaso[row0 + 8];
        float* o0 = out + (size_t)row0 * HW + n0 + nbase + qcol;
        float* o1 = out + (size_t)(row0 + 8) * HW + n0 + nbase + qcol;
        #pragma unroll
        for (int nf = 0; nf < 4; nf++) {
            float2 v0, v1;
            v0.x = fmaxf(acc[mf][nf][0] + bi0, 0.f);
            v0.y = fmaxf(acc[mf][nf][1] + bi0, 0.f);
            v1.x = fmaxf(acc[mf][nf][2] + bi1, 0.f);
            v1.y = fmaxf(acc[mf][nf][3] + bi1, 0.f);
            *(float2*)(o0 + nf * 8) = v0;
            *(float2*)(o1 + nf * 8) = v1;
        }
    }
}

// ---------------- launch ----------------
extern "C" void kernel_launch(void* const* d_in, const int* in_sizes, int n_in,
                              void* d_out, int out_size) {
    const float* x        = (const float*)d_in[0];
    const float* gn_scale = (const float*)d_in[1];
    const float* gn_bias  = (const float*)d_in[2];
    const float* w_proj   = (const float*)d_in[3];
    float* out = (float*)d_out;

    cudaFuncSetAttribute(gemm_mma_kernel,
                         cudaFuncAttributeMaxDynamicSharedMemorySize, GEMM_SMEM);

    haar_kernel<<<256, 256>>>(x);
    foldw_kernel<<<COUT, 256>>>(w_proj, gn_scale, gn_bias);
    dim3 grid(HW / 128, COUT / 128);
    gemm_mma_kernel<<<grid, 256, GEMM_SMEM>>>(out);
}

// round 5
// speedup vs baseline: 4.7897x; 1.4991x over previous
#include <cuda_runtime.h>
#include <cuda_fp16.h>
#include <cstdint>

// ---------------- problem constants ----------------
#define HDIM   256
#define WDIM   256
#define HW     16384          // 128*128 output pixels
#define KB     1024           // K (channels)
#define COUT   512
#define NGROUP 128
#define GSIZE  8
#define GN_EPS 1e-5f
#define TITER  32             // 1024 / 32

// ---------------- device scratch ----------------
__device__ __half g_B[(size_t)KB * HW];        // 32 MB: Y fp16, [k][n]
__device__ __half g_A[(size_t)COUT * KB];      // 1 MB: folded W fp16, [o][k]
__device__ float g_psum[4 * KB];               // per-chunk partial sums
__device__ float g_psumsq[4 * KB];
__device__ float g_biaso[COUT];

// ---------------- PTX helpers (target-generic only) ----------------
__device__ __forceinline__ uint32_t s2u(const void* p) {
    uint32_t a;
    asm("{ .reg .u64 t; cvta.to.shared.u64 t, %1; cvt.u32.u64 %0, t; }" : "=r"(a) : "l"(p));
    return a;
}
__device__ __forceinline__ void cp16(uint32_t dst, const void* src) {
    asm volatile("cp.async.cg.shared.global [%0], [%1], 16;" :: "r"(dst), "l"(src));
}
__device__ __forceinline__ void cp_commit() {
    asm volatile("cp.async.commit_group;" ::: "memory");
}
__device__ __forceinline__ void cp_wait2() {
    asm volatile("cp.async.wait_group 2;" ::: "memory");
}
__device__ __forceinline__ void ldsm4(uint32_t* r, uint32_t a) {
    asm volatile("ldmatrix.sync.aligned.m8n8.x4.shared.b16 {%0,%1,%2,%3}, [%4];"
                 : "=r"(r[0]), "=r"(r[1]), "=r"(r[2]), "=r"(r[3]) : "r"(a));
}
__device__ __forceinline__ void ldsm4t(uint32_t* r, uint32_t a) {
    asm volatile("ldmatrix.sync.aligned.m8n8.x4.trans.shared.b16 {%0,%1,%2,%3}, [%4];"
                 : "=r"(r[0]), "=r"(r[1]), "=r"(r[2]), "=r"(r[3]) : "r"(a));
}
__device__ __forceinline__ void mma16816(float* d, const uint32_t* a, uint32_t b0, uint32_t b1) {
    asm volatile(
        "mma.sync.aligned.m16n8k16.row.col.f32.f16.f16.f32 "
        "{%0,%1,%2,%3}, {%4,%5,%6,%7}, {%8,%9}, {%0,%1,%2,%3};"
        : "+f"(d[0]), "+f"(d[1]), "+f"(d[2]), "+f"(d[3])
        : "r"(a[0]), "r"(a[1]), "r"(a[2]), "r"(a[3]), "r"(b0), "r"(b1));
}

// ---------------- Kernel A: Haar bands -> fp16 + partial stats ----------------
// grid (256 channels, 4 row-chunks); each block: 32 output rows = 4096 pixels.
__global__ __launch_bounds__(256) void haar_kernel(const float* __restrict__ x) {
    const int cx    = blockIdx.x;            // input channel 0..255
    const int chunk = blockIdx.y;            // 0..3
    const float* xp = x + (size_t)cx * (HDIM * WDIM);

    float s0=0.f,s1=0.f,s2=0.f,s3=0.f,q0=0.f,q1=0.f,q2=0.f,q3=0.f;

    const int i2_lo = chunk * 4096;
    const int i2_hi = i2_lo + 4096;
    for (int i2 = i2_lo + threadIdx.x * 2; i2 < i2_hi; i2 += 512) {
        const int h = i2 >> 7;
        const int w = i2 & 127;               // even
        const float4 r0 = *(const float4*)(xp + (size_t)(2*h)   * WDIM + 2*w);
        const float4 r1 = *(const float4*)(xp + (size_t)(2*h+1) * WDIM + 2*w);
        float v0[4], v1[4];
        v0[0] = 0.5f*( r0.x + r0.y + r1.x + r1.y);
        v0[1] = 0.5f*(-r0.x - r0.y + r1.x + r1.y);
        v0[2] = 0.5f*(-r0.x + r0.y - r1.x + r1.y);
        v0[3] = 0.5f*( r0.x - r0.y - r1.x + r1.y);
        v1[0] = 0.5f*( r0.z + r0.w + r1.z + r1.w);
        v1[1] = 0.5f*(-r0.z - r0.w + r1.z + r1.w);
        v1[2] = 0.5f*(-r0.z + r0.w - r1.z + r1.w);
        v1[3] = 0.5f*( r0.z - r0.w - r1.z + r1.w);
        s0 += v0[0]+v1[0]; q0 += v0[0]*v0[0] + v1[0]*v1[0];
        s1 += v0[1]+v1[1]; q1 += v0[1]*v0[1] + v1[1]*v1[1];
        s2 += v0[2]+v1[2]; q2 += v0[2]*v0[2] + v1[2]*v1[2];
        s3 += v0[3]+v1[3]; q3 += v0[3]*v0[3] + v1[3]*v1[3];
        #pragma unroll
        for (int b = 0; b < 4; b++) {
            const size_t c = (size_t)b * 256 + cx;
            *(__half2*)&g_B[c * HW + i2] =
                __halves2half2(__float2half_rn(v0[b]), __float2half_rn(v1[b]));
        }
    }

    __shared__ float red[256];
    float vals[8] = {s0,s1,s2,s3,q0,q1,q2,q3};
    for (int q = 0; q < 8; q++) {
        red[threadIdx.x] = vals[q];
        __syncthreads();
        for (int off = 128; off > 0; off >>= 1) {
            if (threadIdx.x < off) red[threadIdx.x] += red[threadIdx.x + off];
            __syncthreads();
        }
        if (threadIdx.x == 0) {
            const int band = q & 3;
            const int idx = chunk * KB + band * 256 + cx;
            if (q < 4) g_psum[idx]   = red[0];
            else       g_psumsq[idx] = red[0];
        }
        __syncthreads();
    }
}

// ---------------- Kernel B: stats + fold affine into fp16 weights ------
__global__ __launch_bounds__(256) void foldw_kernel(const float* __restrict__ w,
                                                    const float* __restrict__ scale,
                                                    const float* __restrict__ bias) {
    __shared__ float sa[KB], sb[KB];
    const int tid = threadIdx.x;
    if (tid < NGROUP) {
        const int g = tid;
        float s = 0.f, q = 0.f;
        #pragma unroll
        for (int j = 0; j < GSIZE; j++) {
            const int c = g*GSIZE + j;
            #pragma unroll
            for (int ch = 0; ch < 4; ch++) {
                s += g_psum[ch * KB + c];
                q += g_psumsq[ch * KB + c];
            }
        }
        const float inv  = 1.0f / (float)(GSIZE * HW);
        const float mean = s * inv;
        const float var  = q * inv - mean * mean;
        const float rstd = rsqrtf(var + GN_EPS);
        #pragma unroll
        for (int j = 0; j < GSIZE; j++) {
            const int c = g*GSIZE + j;
            const float a = scale[c] * rstd;
            sa[c] = a;
            sb[c] = bias[c] - mean * a;
        }
    }
    __syncthreads();

    const int o = blockIdx.x;                // 0..511
    float part = 0.f;
    for (int c = tid; c < KB; c += 256) {
        const float wv = w[(size_t)o * KB + c];
        g_A[(size_t)o * KB + c] = __float2half_rn(wv * sa[c]);
        part += wv * sb[c];
    }
    __shared__ float red[256];
    red[tid] = part;
    __syncthreads();
    for (int off = 128; off > 0; off >>= 1) {
        if (tid < off) red[tid] += red[tid + off];
        __syncthreads();
    }
    if (tid == 0) g_biaso[o] = red[0];
}

// ---------------- Kernel C: mma.sync fp16 GEMM + bias + ReLU ----
// C[512,16384] = W[512,1024] @ Y[1024,16384]; BM=128 BN=128 BK=32, 8 warps 64x32.
// Stage: A 8KB + B 8KB = 16KB; 4 stages = 64KB.
#define STAGE_BYTES 16384
#define GEMM_SMEM   (4 * STAGE_BYTES)

__device__ __forceinline__ void load_stage(int tid, int j, uint32_t sbase, int m0, int n0) {
    const uint32_t st = sbase + (uint32_t)(j & 3) * STAGE_BYTES;
    const int koff = j << 5;                 // 0..992
    const __half* Ab = g_A + (size_t)m0 * KB + koff;
    const __half* Bb = g_B + (size_t)koff * HW + n0;
    // A: 128 rows(m) x 4 chunks(kc of 8 halves); swizzle unit = m*4 + (kc ^ ((m>>1)&3))
    #pragma unroll
    for (int t = 0; t < 2; t++) {
        const int u = tid + t * 256;
        const int m = u >> 2, kc = u & 3;
        const uint32_t du = (uint32_t)(m * 4 + (kc ^ ((m >> 1) & 3))) * 16;
        cp16(st + du, Ab + (size_t)m * KB + kc * 8);
    }
    // B: 32 rows(k) x 16 chunks(nc of 8 halves); swizzle unit = k*16 + (nc ^ (k&7))
    #pragma unroll
    for (int t = 0; t < 2; t++) {
        const int u = tid + t * 256;
        const int k = u >> 4, nc = u & 15;
        const uint32_t du = (uint32_t)(k * 16 + (nc ^ (k & 7)));
        cp16(st + 8192 + du * 16, Bb + (size_t)k * HW + nc * 8);
    }
}

__global__ __launch_bounds__(256, 2) void gemm_mma_kernel(float* __restrict__ out) {
    extern __shared__ char smem[];
    const uint32_t sbase = s2u(smem);
    const int tid  = threadIdx.x;
    const int wid  = tid >> 5;
    const int lane = tid & 31;
    const int n0 = blockIdx.x * 128;
    const int m0 = blockIdx.y * 128;
    const int wm = wid >> 2;                 // 0..1
    const int wn = wid & 3;                  // 0..3
    const int mbase = wm * 64;
    const int nbase = wn * 32;

    float acc[4][4][4];
    #pragma unroll
    for (int i = 0; i < 4; i++)
        #pragma unroll
        for (int j = 0; j < 4; j++)
            #pragma unroll
            for (int q = 0; q < 4; q++) acc[i][j][q] = 0.f;

    load_stage(tid, 0, sbase, m0, n0); cp_commit();
    load_stage(tid, 1, sbase, m0, n0); cp_commit();
    load_stage(tid, 2, sbase, m0, n0); cp_commit();

    const int r15 = lane & 15;
    const int hi  = lane >> 4;
    const int sA  = (r15 >> 1) & 3;          // A swizzle term

    for (int j = 0; j < TITER; j++) {
        cp_wait2();
        __syncthreads();
        if (j + 3 < TITER) load_stage(tid, j + 3, sbase, m0, n0);
        cp_commit();

        const uint32_t st = sbase + (uint32_t)(j & 3) * STAGE_BYTES;
        #pragma unroll
        for (int kk = 0; kk < 2; kk++) {
            const uint32_t aoff = (uint32_t)(((mbase + r15) * 4 + ((kk * 2 + hi) ^ sA)) * 16);
            uint32_t b[2][4];
            #pragma unroll
            for (int p = 0; p < 2; p++) {
                const int k   = kk * 16 + r15;
                const int ncg = wn * 4 + p * 2 + hi;
                ldsm4t(b[p], st + 8192 + (uint32_t)((k * 16 + (ncg ^ (lane & 7))) * 16));
            }
            uint32_t a[4][4];
            #pragma unroll
            for (int mf = 0; mf < 4; mf++) ldsm4(a[mf], st + aoff + (uint32_t)(mf * 1024));
            #pragma unroll
            for (int mf = 0; mf < 4; mf++)
                #pragma unroll
                for (int nf = 0; nf < 4; nf++)
                    mma16816(acc[mf][nf], a[mf], b[nf >> 1][(nf & 1) * 2],
                             b[nf >> 1][(nf & 1) * 2 + 1]);
        }
    }

    // epilogue: bias + ReLU + float2 stores
    const int qrow = lane >> 2;
    const int qcol = (lane & 3) * 2;
    #pragma unroll
    for (int mf = 0; mf < 4; mf++) {
        const int row0 = m0 + mbase + mf * 16 + qrow;
        const float bi0 = g_biaso[row0];
        const float bi1 = g_biaso[row0 + 8];
        float* o0 = out + (size_t)row0 * HW + n0 + nbase + qcol;
        float* o1 = out + (size_t)(row0 + 8) * HW + n0 + nbase + qcol;
        #pragma unroll
        for (int nf = 0; nf < 4; nf++) {
            float2 v0, v1;
            v0.x = fmaxf(acc[mf][nf][0] + bi0, 0.f);
            v0.y = fmaxf(acc[mf][nf][1] + bi0, 0.f);
            v1.x = fmaxf(acc[mf][nf][2] + bi1, 0.f);
            v1.y = fmaxf(acc[mf][nf][3] + bi1, 0.f);
            *(float2*)(o0 + nf * 8) = v0;
            *(float2*)(o1 + nf * 8) = v1;
        }
    }
}

// ---------------- launch ----------------
extern "C" void kernel_launch(void* const* d_in, const int* in_sizes, int n_in,
                              void* d_out, int out_size) {
    const float* x        = (const float*)d_in[0];
    const float* gn_scale = (const float*)d_in[1];
    const float* gn_bias  = (const float*)d_in[2];
    const float* w_proj   = (const float*)d_in[3];
    float* out = (float*)d_out;

    cudaFuncSetAttribute(gemm_mma_kernel,
                         cudaFuncAttributeMaxDynamicSharedMemorySize, GEMM_SMEM);

    dim3 hgrid(256, 4);
    haar_kernel<<<hgrid, 256>>>(x);
    foldw_kernel<<<COUT, 256>>>(w_proj, gn_scale, gn_bias);
    dim3 grid(HW / 128, COUT / 128);
    gemm_mma_kernel<<<grid, 256, GEMM_SMEM>>>(out);
}

// round 6
// speedup vs baseline: 4.8088x; 1.0040x over previous
#include <cuda_runtime.h>
#include <cuda_fp16.h>
#include <cstdint>

// ---------------- problem constants ----------------
#define HDIM   256
#define WDIM   256
#define HW     16384          // 128*128 output pixels
#define KB     1024           // K (channels)
#define COUT   512
#define NGROUP 128
#define GSIZE  8
#define GN_EPS 1e-5f
#define TITER  16             // 1024 / 64

// ---------------- device scratch ----------------
__device__ __half g_B[(size_t)KB * HW];        // 32 MB: Y fp16, [k][n]
__device__ __half g_A[(size_t)COUT * KB];      // 1 MB: folded W fp16, [o][k]
__device__ float g_psum[4 * KB];               // per-chunk partial sums
__device__ float g_psumsq[4 * KB];
__device__ float g_biaso[COUT];

// ---------------- PTX helpers (target-generic only) ----------------
__device__ __forceinline__ uint32_t s2u(const void* p) {
    uint32_t a;
    asm("{ .reg .u64 t; cvta.to.shared.u64 t, %1; cvt.u32.u64 %0, t; }" : "=r"(a) : "l"(p));
    return a;
}
__device__ __forceinline__ void cp16(uint32_t dst, const void* src) {
    asm volatile("cp.async.cg.shared.global [%0], [%1], 16;" :: "r"(dst), "l"(src));
}
__device__ __forceinline__ void cp_commit() {
    asm volatile("cp.async.commit_group;" ::: "memory");
}
__device__ __forceinline__ void cp_wait1() {
    asm volatile("cp.async.wait_group 1;" ::: "memory");
}
__device__ __forceinline__ void ldsm4(uint32_t* r, uint32_t a) {
    asm volatile("ldmatrix.sync.aligned.m8n8.x4.shared.b16 {%0,%1,%2,%3}, [%4];"
                 : "=r"(r[0]), "=r"(r[1]), "=r"(r[2]), "=r"(r[3]) : "r"(a));
}
__device__ __forceinline__ void ldsm4t(uint32_t* r, uint32_t a) {
    asm volatile("ldmatrix.sync.aligned.m8n8.x4.trans.shared.b16 {%0,%1,%2,%3}, [%4];"
                 : "=r"(r[0]), "=r"(r[1]), "=r"(r[2]), "=r"(r[3]) : "r"(a));
}
__device__ __forceinline__ void mma16816(float* d, const uint32_t* a, uint32_t b0, uint32_t b1) {
    asm volatile(
        "mma.sync.aligned.m16n8k16.row.col.f32.f16.f16.f32 "
        "{%0,%1,%2,%3}, {%4,%5,%6,%7}, {%8,%9}, {%0,%1,%2,%3};"
        : "+f"(d[0]), "+f"(d[1]), "+f"(d[2]), "+f"(d[3])
        : "r"(a[0]), "r"(a[1]), "r"(a[2]), "r"(a[3]), "r"(b0), "r"(b1));
}

// ---------------- Kernel A: Haar bands -> fp16 + partial stats ----------------
// grid (256 channels, 4 row-chunks); block: 32 output rows = 4096 pixels.
// Each thread: 4 consecutive output pixels -> 8B store per band.
__global__ __launch_bounds__(256) void haar_kernel(const float* __restrict__ x) {
    const int cx    = blockIdx.x;            // input channel 0..255
    const int chunk = blockIdx.y;            // 0..3
    const float* xp = x + (size_t)cx * (HDIM * WDIM);

    float s0=0.f,s1=0.f,s2=0.f,s3=0.f,q0=0.f,q1=0.f,q2=0.f,q3=0.f;

    const int i4_lo = chunk * 4096;
    const int i4_hi = i4_lo + 4096;
    for (int i4 = i4_lo + threadIdx.x * 4; i4 < i4_hi; i4 += 1024) {
        const int h = i4 >> 7;
        const int w = i4 & 127;               // multiple of 4
        const float* r0p = xp + (size_t)(2*h)   * WDIM + 2*w;
        const float* r1p = xp + (size_t)(2*h+1) * WDIM + 2*w;
        const float4 a0 = *(const float4*)(r0p);
        const float4 a1 = *(const float4*)(r0p + 4);
        const float4 b0 = *(const float4*)(r1p);
        const float4 b1 = *(const float4*)(r1p + 4);

        // 4 pixels: (x00,x01,x10,x11) tuples
        float v[4][4];   // [pixel][band]
        {
            const float p00[4] = {a0.x, a0.z, a1.x, a1.z};
            const float p01[4] = {a0.y, a0.w, a1.y, a1.w};
            const float p10[4] = {b0.x, b0.z, b1.x, b1.z};
            const float p11[4] = {b0.y, b0.w, b1.y, b1.w};
            #pragma unroll
            for (int p = 0; p < 4; p++) {
                v[p][0] = 0.5f*( p00[p] + p01[p] + p10[p] + p11[p]);
                v[p][1] = 0.5f*(-p00[p] - p01[p] + p10[p] + p11[p]);
                v[p][2] = 0.5f*(-p00[p] + p01[p] - p10[p] + p11[p]);
                v[p][3] = 0.5f*( p00[p] - p01[p] - p10[p] + p11[p]);
            }
        }
        #pragma unroll
        for (int p = 0; p < 4; p++) {
            s0 += v[p][0]; q0 += v[p][0]*v[p][0];
            s1 += v[p][1]; q1 += v[p][1]*v[p][1];
            s2 += v[p][2]; q2 += v[p][2]*v[p][2];
            s3 += v[p][3]; q3 += v[p][3]*v[p][3];
        }
        #pragma unroll
        for (int b = 0; b < 4; b++) {
            const size_t c = (size_t)b * 256 + cx;
            const __half2 h01 = __halves2half2(__float2half_rn(v[0][b]), __float2half_rn(v[1][b]));
            const __half2 h23 = __halves2half2(__float2half_rn(v[2][b]), __float2half_rn(v[3][b]));
            uint2 st;
            st.x = *(const uint32_t*)&h01;
            st.y = *(const uint32_t*)&h23;
            *(uint2*)&g_B[c * HW + i4] = st;
        }
    }

    __shared__ float red[256];
    float vals[8] = {s0,s1,s2,s3,q0,q1,q2,q3};
    for (int q = 0; q < 8; q++) {
        red[threadIdx.x] = vals[q];
        __syncthreads();
        for (int off = 128; off > 0; off >>= 1) {
            if (threadIdx.x < off) red[threadIdx.x] += red[threadIdx.x + off];
            __syncthreads();
        }
        if (threadIdx.x == 0) {
            const int band = q & 3;
            const int idx = chunk * KB + band * 256 + cx;
            if (q < 4) g_psum[idx]   = red[0];
            else       g_psumsq[idx] = red[0];
        }
        __syncthreads();
    }
}

// ---------------- Kernel B: stats + fold affine into fp16 weights ------
__global__ __launch_bounds__(256) void foldw_kernel(const float* __restrict__ w,
                                                    const float* __restrict__ scale,
                                                    const float* __restrict__ bias) {
    __shared__ float sa[KB], sb[KB];
    const int tid = threadIdx.x;
    if (tid < NGROUP) {
        const int g = tid;
        float s = 0.f, q = 0.f;
        #pragma unroll
        for (int j = 0; j < GSIZE; j++) {
            const int c = g*GSIZE + j;
            #pragma unroll
            for (int ch = 0; ch < 4; ch++) {
                s += g_psum[ch * KB + c];
                q += g_psumsq[ch * KB + c];
            }
        }
        const float inv  = 1.0f / (float)(GSIZE * HW);
        const float mean = s * inv;
        const float var  = q * inv - mean * mean;
        const float rstd = rsqrtf(var + GN_EPS);
        #pragma unroll
        for (int j = 0; j < GSIZE; j++) {
            const int c = g*GSIZE + j;
            const float a = scale[c] * rstd;
            sa[c] = a;
            sb[c] = bias[c] - mean * a;
        }
    }
    __syncthreads();

    const int o = blockIdx.x;                // 0..511
    float part = 0.f;
    for (int c = tid; c < KB; c += 256) {
        const float wv = w[(size_t)o * KB + c];
        g_A[(size_t)o * KB + c] = __float2half_rn(wv * sa[c]);
        part += wv * sb[c];
    }
    __shared__ float red[256];
    red[tid] = part;
    __syncthreads();
    for (int off = 128; off > 0; off >>= 1) {
        if (tid < off) red[tid] += red[tid + off];
        __syncthreads();
    }
    if (tid == 0) g_biaso[o] = red[0];
}

// ---------------- Kernel C: mma.sync fp16 GEMM + bias + ReLU ----
// C[512,16384] = W[512,1024] @ Y[1024,16384]; BM=128 BN=128 BK=64, 8 warps 64x32.
// Stage: A 16KB + B 16KB = 32KB; 3 stages = 96KB.
#define STAGE_BYTES 32768
#define GEMM_SMEM   (3 * STAGE_BYTES)

__device__ __forceinline__ void load_stage(int tid, int j, uint32_t sbase, int m0, int n0) {
    const uint32_t st = sbase + (uint32_t)(j % 3) * STAGE_BYTES;
    const int koff = j << 6;                 // 0..960
    const __half* Ab = g_A + (size_t)m0 * KB + koff;
    const __half* Bb = g_B + (size_t)koff * HW + n0;
    // A: 128 rows(m) x 8 chunks(kc of 8 halves); swizzle unit = m*8 + (kc ^ (m&7))
    #pragma unroll
    for (int t = 0; t < 4; t++) {
        const int u = tid + t * 256;
        const int m = u >> 3, kc = u & 7;
        const uint32_t du = (uint32_t)(m * 8 + (kc ^ (m & 7))) * 16;
        cp16(st + du, Ab + (size_t)m * KB + kc * 8);
    }
    // B: 64 rows(k) x 16 chunks(nc of 8 halves); swizzle unit = k*16 + (nc ^ (k&7))
    #pragma unroll
    for (int t = 0; t < 4; t++) {
        const int u = tid + t * 256;
        const int k = u >> 4, nc = u & 15;
        const uint32_t du = (uint32_t)(k * 16 + (nc ^ (k & 7)));
        cp16(st + 16384 + du * 16, Bb + (size_t)k * HW + nc * 8);
    }
}

__global__ __launch_bounds__(256, 2) void gemm_mma_kernel(float* __restrict__ out) {
    extern __shared__ char smem[];
    const uint32_t sbase = s2u(smem);
    const int tid  = threadIdx.x;
    const int wid  = tid >> 5;
    const int lane = tid & 31;
    const int n0 = blockIdx.x * 128;
    const int m0 = blockIdx.y * 128;
    const int wm = wid >> 2;                 // 0..1
    const int wn = wid & 3;                  // 0..3
    const int mbase = wm * 64;
    const int nbase = wn * 32;

    float acc[4][4][4];
    #pragma unroll
    for (int i = 0; i < 4; i++)
        #pragma unroll
        for (int j = 0; j < 4; j++)
            #pragma unroll
            for (int q = 0; q < 4; q++) acc[i][j][q] = 0.f;

    load_stage(tid, 0, sbase, m0, n0); cp_commit();
    load_stage(tid, 1, sbase, m0, n0); cp_commit();

    const int r15 = lane & 15;
    const int hi  = lane >> 4;
    const int s7  = r15 & 7;                 // swizzle term (row&7 / k&7)

    for (int j = 0; j < TITER; j++) {
        cp_wait1();
        __syncthreads();
        if (j + 2 < TITER) load_stage(tid, j + 2, sbase, m0, n0);
        cp_commit();

        const uint32_t st = sbase + (uint32_t)(j % 3) * STAGE_BYTES;
        #pragma unroll
        for (int kk = 0; kk < 4; kk++) {
            const uint32_t aoff = (uint32_t)(((mbase + r15) * 8 + ((kk * 2 + hi) ^ s7)) * 16);
            uint32_t b[2][4];
            #pragma unroll
            for (int p = 0; p < 2; p++) {
                const int k   = kk * 16 + r15;
                const int ncg = wn * 4 + p * 2 + hi;
                ldsm4t(b[p], st + 16384 + (uint32_t)((k * 16 + (ncg ^ s7)) * 16));
            }
            uint32_t a[4][4];
            #pragma unroll
            for (int mf = 0; mf < 4; mf++) ldsm4(a[mf], st + aoff + (uint32_t)(mf * 2048));
            #pragma unroll
            for (int mf = 0; mf < 4; mf++)
                #pragma unroll
                for (int nf = 0; nf < 4; nf++)
                    mma16816(acc[mf][nf], a[mf], b[nf >> 1][(nf & 1) * 2],
                             b[nf >> 1][(nf & 1) * 2 + 1]);
        }
    }

    // epilogue: bias + ReLU + float2 stores
    const int qrow = lane >> 2;
    const int qcol = (lane & 3) * 2;
    #pragma unroll
    for (int mf = 0; mf < 4; mf++) {
        const int row0 = m0 + mbase + mf * 16 + qrow;
        const float bi0 = g_biaso[row0];
        const float bi1 = g_biaso[row0 + 8];
        float* o0 = out + (size_t)row0 * HW + n0 + nbase + qcol;
        float* o1 = out + (size_t)(row0 + 8) * HW + n0 + nbase + qcol;
        #pragma unroll
        for (int nf = 0; nf < 4; nf++) {
            float2 v0, v1;
            v0.x = fmaxf(acc[mf][nf][0] + bi0, 0.f);
            v0.y = fmaxf(acc[mf][nf][1] + bi0, 0.f);
            v1.x = fmaxf(acc[mf][nf][2] + bi1, 0.f);
            v1.y = fmaxf(acc[mf][nf][3] + bi1, 0.f);
            *(float2*)(o0 + nf * 8) = v0;
            *(float2*)(o1 + nf * 8) = v1;
        }
    }
}

// ---------------- launch ----------------
extern "C" void kernel_launch(void* const* d_in, const int* in_sizes, int n_in,
                              void* d_out, int out_size) {
    const float* x        = (const float*)d_in[0];
    const float* gn_scale = (const float*)d_in[1];
    const float* gn_bias  = (const float*)d_in[2];
    const float* w_proj   = (const float*)d_in[3];
    float* out = (float*)d_out;

    cudaFuncSetAttribute(gemm_mma_kernel,
                         cudaFuncAttributeMaxDynamicSharedMemorySize, GEMM_SMEM);

    dim3 hgrid(256, 4);
    haar_kernel<<<hgrid, 256>>>(x);
    foldw_kernel<<<COUT, 256>>>(w_proj, gn_scale, gn_bias);
    dim3 grid(HW / 128, COUT / 128);
    gemm_mma_kernel<<<grid, 256, GEMM_SMEM>>>(out);
}